// round 7
// baseline (speedup 1.0000x reference)
#include <cuda_runtime.h>

// AdvancedLearnableEntropyPooling2D: 2x2/stride-2 entropy pooling, NHWC.
// x: [32, 256, 256, 128] f32 -> out: [32, 128, 128, 128] f32
// out[b,ho,wo,c] = entropy(softmax over 2x2 window at channel c) * w[c] + bias[c]
//
// One warp per QUAD of horizontally-adjacent output pixels:
//   - per input row the warp reads 4KB contiguous (8 cols x 512B), MLP=16
//   - output store = 2KB contiguous per warp
// All indexing in 32-bit (input is 2^26 float4 elems < 2^31).
// Entropy via logS identity: H = log(S) - (sum e_i*d_i)/S  (6 MUFU/scalar).

static __device__ __forceinline__ float entropy4(float a0, float a1, float a2, float a3) {
    float m  = fmaxf(fmaxf(a0, a1), fmaxf(a2, a3));
    float d0 = a0 - m, d1 = a1 - m, d2 = a2 - m, d3 = a3 - m;
    float e0 = __expf(d0), e1 = __expf(d1), e2 = __expf(d2), e3 = __expf(d3);
    float S  = (e0 + e1) + (e2 + e3);
    float t  = fmaf(e0, d0, fmaf(e1, d1, fmaf(e2, d2, e3 * d3)));
    return __logf(S) - t * __fdividef(1.0f, S);
}

__global__ void __launch_bounds__(256)
entropy_pool_kernel(const float4* __restrict__ x,
                    const float4* __restrict__ wgt,
                    const float4* __restrict__ bias,
                    float4* __restrict__ out) {
    const int W   = 256;       // input width
    const int Ho  = 128, Wo = 128;
    const int CB  = 32;        // 128 channels / 4 per float4
    const int WoQ = Wo / 4;    // pixel-quads per output row = 32

    int gtid = blockIdx.x * blockDim.x + threadIdx.x;
    int lane = gtid & 31;      // channel group 0..31
    int wid  = gtid >> 5;      // global warp id == output pixel-quad id

    // wid -> (b, ho, woq); WoQ=32 (5 bits), Ho=128 (7 bits), B=32
    int woq = wid & (WoQ - 1);
    int t   = wid >> 5;
    int ho  = t & (Ho - 1);
    int b   = t >> 7;

    // input rows 2*ho, 2*ho+1; input cols 8*woq .. 8*woq+7  (32-bit offsets)
    const int rowpitch = W * CB;                         // 8192 float4/row
    int base = (b * 256 + 2 * ho) * rowpitch + (8 * woq) * CB + lane;
    const float4* r0 = x + base;
    const float4* r1 = r0 + rowpitch;

    // 16 independent streaming loads, each a full 512B warp segment
    float4 a0 = __ldcs(r0);            float4 a1 = __ldcs(r0 + CB);
    float4 b0 = __ldcs(r0 + 2 * CB);   float4 b1 = __ldcs(r0 + 3 * CB);
    float4 c0 = __ldcs(r0 + 4 * CB);   float4 c1 = __ldcs(r0 + 5 * CB);
    float4 d0 = __ldcs(r0 + 6 * CB);   float4 d1 = __ldcs(r0 + 7 * CB);
    float4 a2 = __ldcs(r1);            float4 a3 = __ldcs(r1 + CB);
    float4 b2 = __ldcs(r1 + 2 * CB);   float4 b3 = __ldcs(r1 + 3 * CB);
    float4 c2 = __ldcs(r1 + 4 * CB);   float4 c3 = __ldcs(r1 + 5 * CB);
    float4 d2 = __ldcs(r1 + 6 * CB);   float4 d3 = __ldcs(r1 + 7 * CB);

    float4 wv = wgt[lane];
    float4 bv = bias[lane];

    float4 o0, o1, o2, o3;
    o0.x = fmaf(entropy4(a0.x, a1.x, a2.x, a3.x), wv.x, bv.x);
    o0.y = fmaf(entropy4(a0.y, a1.y, a2.y, a3.y), wv.y, bv.y);
    o0.z = fmaf(entropy4(a0.z, a1.z, a2.z, a3.z), wv.z, bv.z);
    o0.w = fmaf(entropy4(a0.w, a1.w, a2.w, a3.w), wv.w, bv.w);

    o1.x = fmaf(entropy4(b0.x, b1.x, b2.x, b3.x), wv.x, bv.x);
    o1.y = fmaf(entropy4(b0.y, b1.y, b2.y, b3.y), wv.y, bv.y);
    o1.z = fmaf(entropy4(b0.z, b1.z, b2.z, b3.z), wv.z, bv.z);
    o1.w = fmaf(entropy4(b0.w, b1.w, b2.w, b3.w), wv.w, bv.w);

    o2.x = fmaf(entropy4(c0.x, c1.x, c2.x, c3.x), wv.x, bv.x);
    o2.y = fmaf(entropy4(c0.y, c1.y, c2.y, c3.y), wv.y, bv.y);
    o2.z = fmaf(entropy4(c0.z, c1.z, c2.z, c3.z), wv.z, bv.z);
    o2.w = fmaf(entropy4(c0.w, c1.w, c2.w, c3.w), wv.w, bv.w);

    o3.x = fmaf(entropy4(d0.x, d1.x, d2.x, d3.x), wv.x, bv.x);
    o3.y = fmaf(entropy4(d0.y, d1.y, d2.y, d3.y), wv.y, bv.y);
    o3.z = fmaf(entropy4(d0.z, d1.z, d2.z, d3.z), wv.z, bv.z);
    o3.w = fmaf(entropy4(d0.w, d1.w, d2.w, d3.w), wv.w, bv.w);

    // 4 contiguous output pixels (wo = 4*woq .. +3): 2KB per warp
    float4* op = out + ((b * Ho + ho) * Wo + 4 * woq) * CB + lane;
    __stcs(op,          o0);
    __stcs(op + CB,     o1);
    __stcs(op + 2 * CB, o2);
    __stcs(op + 3 * CB, o3);
}

extern "C" void kernel_launch(void* const* d_in, const int* in_sizes, int n_in,
                              void* d_out, int out_size) {
    const float4* x    = (const float4*)d_in[0];
    const float4* wgt  = (const float4*)d_in[1];
    const float4* bias = (const float4*)d_in[2];
    float4* out        = (float4*)d_out;

    // warps = 32 * 128 * 32 = 131072 pixel-quads -> 4,194,304 threads
    // 256 threads/block -> 16384 blocks
    entropy_pool_kernel<<<16384, 256>>>(x, wgt, bias, out);
}